// round 15
// baseline (speedup 1.0000x reference)
#include <cuda_runtime.h>
#include <cuda_bf16.h>
#include <cuda_fp16.h>
#include <cstdint>

// Problem constants: B=1, T=8, C=64, H=W=32 -> N=8192 tokens, F=10
#define N_TOK 8192
#define NF 10
#define C_DIM 64
#define NT_TILES 64                    // m-tiles of 128
#define M_SPLIT 8
#define TILES_PER_CTA (NT_TILES / M_SPLIT)   // 8
#define PART_STRIDE (N_TOK * NF)       // 81920 floats per chunk, output-linear layout

// ---------------- device scratch (static; zero-init covers all pad slots) ----------------
__device__ uint32_t g_qs[N_TOK * 8];             // Q rows: 16 fp16 (k=f: qh, 10..15 = 0)
__device__ uint32_t g_kc[NT_TILES * 128 * 8];    // K tiles: [tile][m][16 fp16] (k=f: kh)
__device__ uint32_t g_vc[NT_TILES * 8 * 64];     // V tiles: [tile][f(8)][128 fp16 over m]
__device__ float    g_v89[NT_TILES * 128 * 2];   // V f=8,9 fp32: [tile][m][2]
__device__ float    g_part[M_SPLIT * PART_STRIDE]; // [chunk][(t*NF+f)*1024 + hw]

// ---------------- helpers ----------------
__device__ __forceinline__ void mma_f16(float* o,
                                        uint32_t a0, uint32_t a1, uint32_t a2, uint32_t a3,
                                        uint32_t b0, uint32_t b1) {
    asm volatile("mma.sync.aligned.m16n8k16.row.col.f32.f16.f16.f32 "
                 "{%0,%1,%2,%3}, {%4,%5,%6,%7}, {%8,%9}, {%0,%1,%2,%3};"
                 : "+f"(o[0]), "+f"(o[1]), "+f"(o[2]), "+f"(o[3])
                 : "r"(a0), "r"(a1), "r"(a2), "r"(a3), "r"(b0), "r"(b1));
}
__device__ __forceinline__ void mma_f16_h(uint32_t& d0, uint32_t& d1,
                                          uint32_t a0, uint32_t a1, uint32_t a2, uint32_t a3,
                                          uint32_t b0, uint32_t b1) {
    asm volatile("mma.sync.aligned.m16n8k16.row.col.f16.f16.f16.f16 "
                 "{%0,%1}, {%2,%3,%4,%5}, {%6,%7}, {%8,%9};"
                 : "=&r"(d0), "=&r"(d1)
                 : "r"(a0), "r"(a1), "r"(a2), "r"(a3), "r"(b0), "r"(b1),
                   "r"(0u), "r"(0u));
}
__device__ __forceinline__ void ldsm4(uint32_t& r0, uint32_t& r1, uint32_t& r2, uint32_t& r3,
                                      uint32_t addr) {
    asm volatile("ldmatrix.sync.aligned.m8n8.x4.shared.b16 {%0,%1,%2,%3}, [%4];"
                 : "=r"(r0), "=r"(r1), "=r"(r2), "=r"(r3) : "r"(addr));
}
__device__ __forceinline__ void ldsm2(uint32_t& r0, uint32_t& r1, uint32_t addr) {
    asm volatile("ldmatrix.sync.aligned.m8n8.x2.shared.b16 {%0,%1}, [%2];"
                 : "=r"(r0), "=r"(r1) : "r"(addr));
}
__device__ __forceinline__ uint32_t packh(float lo, float hi) {
    uint32_t r;   // first src -> upper half
    asm("cvt.rn.f16x2.f32 %0, %1, %2;" : "=r"(r) : "f"(hi), "f"(lo));
    return r;
}
__device__ __forceinline__ uint32_t relu2h(uint32_t p) {
    __half2 z = __half2half2(__ushort_as_half((unsigned short)0));
    __half2 v = __hmax2(*reinterpret_cast<__half2*>(&p), z);
    return *reinterpret_cast<uint32_t*>(&v);
}
__device__ __forceinline__ void cp16(uint32_t saddr, const void* g) {
    asm volatile("cp.async.cg.shared.global [%0], [%1], 16;" :: "r"(saddr), "l"(g));
}
#define CP_COMMIT() asm volatile("cp.async.commit_group;" ::: "memory")
#define CP_WAIT(n)  asm volatile("cp.async.wait_group %0;" :: "n"(n) : "memory")

// ---------------- Kernel 1: projections -> operand images (latency-overlapped) ----------------
__global__ __launch_bounds__(256) void proj_kernel(
    const float* __restrict__ in1, const float* __restrict__ in2,
    const float* __restrict__ w1, const float* __restrict__ b1,
    const float* __restrict__ w2, const float* __restrict__ b2,
    const float* __restrict__ w3, const float* __restrict__ b3)
{
    __shared__ float ws[NF * C_DIM];
    __shared__ float sbias[NF];
    __shared__ float red[4 * 64 * NF];

    const int which = blockIdx.y;
    const float* w    = (which == 0) ? w1 : (which == 1) ? w2 : w3;
    const float* bias = (which == 0) ? b1 : (which == 1) ? b2 : b3;
    const float* x    = (which == 1) ? in2 : in1;

    const int tid  = threadIdx.x;
    const int part = tid >> 6;                // 0..3 (warp-uniform)
    const int ln   = tid & 63;
    const int n    = blockIdx.x * 64 + ln;
    const int t    = n >> 10;
    const int hw   = n & 1023;
    const float* xp = x + t * (C_DIM * 1024) + hw;
    const int c0 = part * 16;

    float xv[16];
#pragma unroll
    for (int cc = 0; cc < 16; cc++)
        xv[cc] = xp[(c0 + cc) << 10];

    for (int i = tid; i < NF * C_DIM; i += 256) ws[i] = w[i];
    if (tid < NF) sbias[tid] = bias[tid];
    __syncthreads();

    float acc[NF];
#pragma unroll
    for (int f = 0; f < NF; f++) acc[f] = 0.f;
#pragma unroll
    for (int cc = 0; cc < 16; cc++) {
        const int c = c0 + cc;
        float a = xv[cc];
#pragma unroll
        for (int f = 0; f < NF; f++)
            acc[f] = fmaf(ws[f * C_DIM + c], a, acc[f]);
    }
#pragma unroll
    for (int f = 0; f < NF; f++)
        red[part * (64 * NF) + ln * NF + f] = acc[f];
    __syncthreads();

    if (which != 2) {
        uint32_t* dst32 = (which == 0) ? g_qs : g_kc;
        for (int idx = tid; idx < 64 * 5; idx += 256) {
            const int ln2 = idx / 5;
            const int p   = idx % 5;
            const int f0  = 2 * p;
            const int j0  = ln2 * NF + f0;
            float s0 = red[j0] + red[64 * NF + j0] + red[2 * 64 * NF + j0]
                     + red[3 * 64 * NF + j0] + sbias[f0];
            float s1 = red[j0 + 1] + red[64 * NF + j0 + 1] + red[2 * 64 * NF + j0 + 1]
                     + red[3 * 64 * NF + j0 + 1] + sbias[f0 + 1];
            const int nn = blockIdx.x * 64 + ln2;
            uint32_t pk = packh(s0, s1);
            if (which == 0) {
                dst32[(size_t)nn * 8 + p] = pk;
            } else {
                const int tile = nn >> 7, m = nn & 127;
                dst32[(size_t)(tile * 128 + m) * 8 + p] = pk;
            }
        }
    } else {
        uint16_t* vc = reinterpret_cast<uint16_t*>(g_vc);
        for (int idx = tid; idx < 64 * 9; idx += 256) {
            const int ln2 = idx / 9;
            const int p   = idx % 9;
            const int nn  = blockIdx.x * 64 + ln2;
            const int tile = nn >> 7, m = nn & 127;
            if (p < 8) {
                const int j = ln2 * NF + p;
                float s = red[j] + red[64 * NF + j] + red[2 * 64 * NF + j]
                        + red[3 * 64 * NF + j] + sbias[p];
                vc[(size_t)tile * 1024 + p * 128 + m] = __half_as_ushort(__float2half_rn(s));
            } else {
                const int j = ln2 * NF + 8;
                float s8 = red[j] + red[64 * NF + j] + red[2 * 64 * NF + j]
                         + red[3 * 64 * NF + j] + sbias[8];
                float s9 = red[j + 1] + red[64 * NF + j + 1] + red[2 * 64 * NF + j + 1]
                         + red[3 * 64 * NF + j + 1] + sbias[9];
                reinterpret_cast<float2*>(g_v89)[(size_t)tile * 128 + m] = make_float2(s8, s9);
            }
        }
    }
}

// ---------------- Kernel 2: mma.sync flash relu-attention ----------------
__global__ __launch_bounds__(256, 4) void attn_kernel()
{
    __shared__ __align__(16) uint32_t sK[2][128 * 12];   // padded stride 12 words
    __shared__ __align__(16) uint32_t sV[2][8 * 68];     // padded stride 68 words
    __shared__ __align__(16) float sV89[2][256];         // [m][2] fp32

    const int tid  = threadIdx.x;
    const int wid  = tid >> 5;
    const int lane = tid & 31;
    const int n0   = blockIdx.x * 128;
    const int my   = blockIdx.y;
    const int t0   = my * TILES_PER_CTA;

    const int rq = n0 + wid * 16 + (lane >> 2);
    const int l4 = lane & 3;
    uint32_t a_q[4];
    a_q[0] = g_qs[rq * 8 + l4];
    a_q[1] = g_qs[(rq + 8) * 8 + l4];
    a_q[2] = g_qs[rq * 8 + 4 + l4];
    a_q[3] = g_qs[(rq + 8) * 8 + 4 + l4];

    float O0a[4] = {0.f, 0.f, 0.f, 0.f};
    float O0b[4] = {0.f, 0.f, 0.f, 0.f};
    float o89[4] = {0.f, 0.f, 0.f, 0.f};

    const uint32_t kRowOff = (uint32_t)(((lane & 7) + ((lane >> 4) << 3)) * 12 + ((lane >> 3) & 1) * 4);
    const uint32_t vRowOff = (uint32_t)((lane & 7) * 68 + ((lane >> 3) & 1) * 4);

    auto stage = [&](int buf, int tile) {
        const char* kbase = reinterpret_cast<const char*>(g_kc) + (size_t)tile * 4096;
        const char* vbase = reinterpret_cast<const char*>(g_vc) + (size_t)tile * 2048;
        const char* v89b  = reinterpret_cast<const char*>(g_v89) + (size_t)tile * 1024;
        {
            uint32_t sa = (uint32_t)__cvta_generic_to_shared(
                &sK[buf][(tid >> 1) * 12 + (tid & 1) * 4]);
            cp16(sa, kbase + tid * 16);
        }
        if (tid < 128) {
            int f = tid >> 4, w4 = tid & 15;
            uint32_t sa = (uint32_t)__cvta_generic_to_shared(&sV[buf][f * 68 + w4 * 4]);
            cp16(sa, vbase + tid * 16);
        } else if (tid < 192) {
            int c2 = tid - 128;
            uint32_t sa = (uint32_t)__cvta_generic_to_shared(&sV89[buf][c2 * 4]);
            cp16(sa, v89b + c2 * 16);
        }
    };

    stage(0, t0);
    CP_COMMIT();

    for (int i = 0; i < TILES_PER_CTA; i++) {
        if (i + 1 < TILES_PER_CTA) {
            stage((i + 1) & 1, t0 + i + 1);
            CP_COMMIT();
            CP_WAIT(1);
        } else {
            CP_WAIT(0);
        }
        __syncthreads();

        const int buf = i & 1;
        const uint32_t kBase  = (uint32_t)__cvta_generic_to_shared(&sK[buf][0]) + kRowOff * 4;
        const uint32_t vBaseH = (uint32_t)__cvta_generic_to_shared(&sV[buf][0]) + vRowOff * 4;

#pragma unroll
        for (int ns4 = 0; ns4 < 8; ns4++) {
            uint32_t b0, b1, b2, b3;
            ldsm4(b0, b1, b2, b3, kBase + (uint32_t)ns4 * 768);

            uint32_t p0, p1, p2, p3;
            mma_f16_h(p0, p1, a_q[0], a_q[1], a_q[2], a_q[3], b0, b1);
            mma_f16_h(p2, p3, a_q[0], a_q[1], a_q[2], a_q[3], b2, b3);

            uint32_t sh0 = relu2h(p0), sh1 = relu2h(p1);
            uint32_t sh2 = relu2h(p2), sh3 = relu2h(p3);

            uint32_t vh0, vh1;
            ldsm2(vh0, vh1, vBaseH + (uint32_t)ns4 * 32);

            if (ns4 & 1) mma_f16(O0b, sh0, sh1, sh2, sh3, vh0, vh1);
            else         mma_f16(O0a, sh0, sh1, sh2, sh3, vh0, vh1);

            float2 f0p = __half22float2(*reinterpret_cast<__half2*>(&sh0));
            float2 f1p = __half22float2(*reinterpret_cast<__half2*>(&sh1));
            float2 f2p = __half22float2(*reinterpret_cast<__half2*>(&sh2));
            float2 f3p = __half22float2(*reinterpret_cast<__half2*>(&sh3));
            float c0 = f0p.x, c1 = f0p.y, c2 = f1p.x, c3 = f1p.y;
            float e0 = f2p.x, e1 = f2p.y, e2 = f3p.x, e3 = f3p.y;

            const float4 va = *reinterpret_cast<const float4*>(&sV89[buf][(16 * ns4 + 2 * l4) * 2]);
            const float4 vb = *reinterpret_cast<const float4*>(&sV89[buf][(16 * ns4 + 8 + 2 * l4) * 2]);
            o89[0] = fmaf(c0, va.x, fmaf(c1, va.z, fmaf(e0, vb.x, fmaf(e1, vb.z, o89[0]))));
            o89[1] = fmaf(c0, va.y, fmaf(c1, va.w, fmaf(e0, vb.y, fmaf(e1, vb.w, o89[1]))));
            o89[2] = fmaf(c2, va.x, fmaf(c3, va.z, fmaf(e2, vb.x, fmaf(e3, vb.z, o89[2]))));
            o89[3] = fmaf(c2, va.y, fmaf(c3, va.w, fmaf(e2, vb.y, fmaf(e3, vb.w, o89[3]))));
        }
        __syncthreads();
    }

#pragma unroll
    for (int d = 1; d < 4; d <<= 1) {
#pragma unroll
        for (int j = 0; j < 4; j++)
            o89[j] += __shfl_xor_sync(0xffffffffu, o89[j], d);
    }

    // ---- epilogue: output-linear layout [(t*NF+f)*1024 + hw] ----
    {
        float* po = g_part + (size_t)my * PART_STRIDE;
        // all 128 rows of this CTA share the same t (n0 is a multiple of 128)
        const int tq   = rq >> 10;
        const int hw0  = rq & 1023;            // row A; row B = hw0 + 8 (same t)
        const int base = tq * (NF * 1024) + hw0;
        const int f0   = l4 * 2;
        po[base + f0 * 1024]             = O0a[0] + O0b[0];
        po[base + (f0 + 1) * 1024]       = O0a[1] + O0b[1];
        po[base + 8 + f0 * 1024]         = O0a[2] + O0b[2];
        po[base + 8 + (f0 + 1) * 1024]   = O0a[3] + O0b[3];
        if (l4 == 0) {
            po[base + 8 * 1024]          = o89[0];
            po[base + 9 * 1024]          = o89[1];
            po[base + 8 + 8 * 1024]      = o89[2];
            po[base + 8 + 9 * 1024]      = o89[3];
        }
    }
}

// ---------------- Kernel 3: fully-coalesced float4 reduce ----------------
__global__ __launch_bounds__(256) void reduce_kernel(float* __restrict__ out)
{
    const int idx = blockIdx.x * blockDim.x + threadIdx.x;   // < 20480 float4s
    const float4* p = reinterpret_cast<const float4*>(g_part);
    float4 s = p[idx];
#pragma unroll
    for (int c = 1; c < M_SPLIT; c++) {
        float4 v = p[(size_t)c * (PART_STRIDE / 4) + idx];
        s.x += v.x; s.y += v.y; s.z += v.z; s.w += v.w;
    }
    reinterpret_cast<float4*>(out)[idx] = s;
}

extern "C" void kernel_launch(void* const* d_in, const int* in_sizes, int n_in,
                              void* d_out, int out_size)
{
    const float* in1 = (const float*)d_in[0];
    const float* in2 = (const float*)d_in[1];
    const float* w1  = (const float*)d_in[2];
    const float* b1  = (const float*)d_in[3];
    const float* w2  = (const float*)d_in[4];
    const float* b2  = (const float*)d_in[5];
    const float* w3  = (const float*)d_in[6];
    const float* b3  = (const float*)d_in[7];

    dim3 pgrid(N_TOK / 64, 3);
    proj_kernel<<<pgrid, 256>>>(in1, in2, w1, b1, w2, b2, w3, b3);

    dim3 agrid(N_TOK / 128, M_SPLIT);
    attn_kernel<<<agrid, 256>>>();

    reduce_kernel<<<(N_TOK * NF / 4) / 256, 256>>>((float*)d_out);
}

// round 16
// speedup vs baseline: 1.2452x; 1.2452x over previous
#include <cuda_runtime.h>
#include <cuda_bf16.h>
#include <cuda_fp16.h>
#include <cstdint>

// Problem constants: B=1, T=8, C=64, H=W=32 -> N=8192 tokens, F=10
#define N_TOK 8192
#define NF 10
#define C_DIM 64
#define NT_TILES 64                    // m-tiles of 128
#define M_SPLIT 8
#define TILES_PER_CTA (NT_TILES / M_SPLIT)   // 8
#define PART_STRIDE (N_TOK * NF)       // 81920 floats per chunk, output-linear layout

// ---------------- device scratch (static; zero-init covers all pad slots) ----------------
__device__ uint32_t g_qs[N_TOK * 8];             // Q rows: 16 fp16 (k=f: qh, 10..15 = 0)
__device__ uint32_t g_kc[NT_TILES * 128 * 8];    // K tiles: [tile][m][16 fp16] (k=f: kh)
__device__ uint32_t g_vc[NT_TILES * 16 * 64];    // V tiles: [tile][f(16)][128 fp16 over m], f10..15 = 0
__device__ float    g_part[M_SPLIT * PART_STRIDE]; // [chunk][(t*NF+f)*1024 + hw]

// ---------------- helpers ----------------
__device__ __forceinline__ void mma_f16(float* o,
                                        uint32_t a0, uint32_t a1, uint32_t a2, uint32_t a3,
                                        uint32_t b0, uint32_t b1) {
    asm volatile("mma.sync.aligned.m16n8k16.row.col.f32.f16.f16.f32 "
                 "{%0,%1,%2,%3}, {%4,%5,%6,%7}, {%8,%9}, {%0,%1,%2,%3};"
                 : "+f"(o[0]), "+f"(o[1]), "+f"(o[2]), "+f"(o[3])
                 : "r"(a0), "r"(a1), "r"(a2), "r"(a3), "r"(b0), "r"(b1));
}
__device__ __forceinline__ void mma_f16_h(uint32_t& d0, uint32_t& d1,
                                          uint32_t a0, uint32_t a1, uint32_t a2, uint32_t a3,
                                          uint32_t b0, uint32_t b1) {
    asm volatile("mma.sync.aligned.m16n8k16.row.col.f16.f16.f16.f16 "
                 "{%0,%1}, {%2,%3,%4,%5}, {%6,%7}, {%8,%9};"
                 : "=&r"(d0), "=&r"(d1)
                 : "r"(a0), "r"(a1), "r"(a2), "r"(a3), "r"(b0), "r"(b1),
                   "r"(0u), "r"(0u));
}
__device__ __forceinline__ void ldsm4(uint32_t& r0, uint32_t& r1, uint32_t& r2, uint32_t& r3,
                                      uint32_t addr) {
    asm volatile("ldmatrix.sync.aligned.m8n8.x4.shared.b16 {%0,%1,%2,%3}, [%4];"
                 : "=r"(r0), "=r"(r1), "=r"(r2), "=r"(r3) : "r"(addr));
}
__device__ __forceinline__ uint32_t packh(float lo, float hi) {
    uint32_t r;   // first src -> upper half
    asm("cvt.rn.f16x2.f32 %0, %1, %2;" : "=r"(r) : "f"(hi), "f"(lo));
    return r;
}
__device__ __forceinline__ uint32_t relu2h(uint32_t p) {
    __half2 z = __half2half2(__ushort_as_half((unsigned short)0));
    __half2 v = __hmax2(*reinterpret_cast<__half2*>(&p), z);
    return *reinterpret_cast<uint32_t*>(&v);
}
__device__ __forceinline__ void cp16(uint32_t saddr, const void* g) {
    asm volatile("cp.async.cg.shared.global [%0], [%1], 16;" :: "r"(saddr), "l"(g));
}
#define CP_COMMIT() asm volatile("cp.async.commit_group;" ::: "memory")
#define CP_WAIT(n)  asm volatile("cp.async.wait_group %0;" :: "n"(n) : "memory")

// ---------------- Kernel 1: projections -> operand images (latency-overlapped) ----------------
__global__ __launch_bounds__(256) void proj_kernel(
    const float* __restrict__ in1, const float* __restrict__ in2,
    const float* __restrict__ w1, const float* __restrict__ b1,
    const float* __restrict__ w2, const float* __restrict__ b2,
    const float* __restrict__ w3, const float* __restrict__ b3)
{
    __shared__ float ws[NF * C_DIM];
    __shared__ float sbias[NF];
    __shared__ float red[4 * 64 * NF];

    const int which = blockIdx.y;
    const float* w    = (which == 0) ? w1 : (which == 1) ? w2 : w3;
    const float* bias = (which == 0) ? b1 : (which == 1) ? b2 : b3;
    const float* x    = (which == 1) ? in2 : in1;

    const int tid  = threadIdx.x;
    const int part = tid >> 6;                // 0..3 (warp-uniform)
    const int ln   = tid & 63;
    const int n    = blockIdx.x * 64 + ln;
    const int t    = n >> 10;
    const int hw   = n & 1023;
    const float* xp = x + t * (C_DIM * 1024) + hw;
    const int c0 = part * 16;

    float xv[16];
#pragma unroll
    for (int cc = 0; cc < 16; cc++)
        xv[cc] = xp[(c0 + cc) << 10];

    for (int i = tid; i < NF * C_DIM; i += 256) ws[i] = w[i];
    if (tid < NF) sbias[tid] = bias[tid];
    __syncthreads();

    float acc[NF];
#pragma unroll
    for (int f = 0; f < NF; f++) acc[f] = 0.f;
#pragma unroll
    for (int cc = 0; cc < 16; cc++) {
        const int c = c0 + cc;
        float a = xv[cc];
#pragma unroll
        for (int f = 0; f < NF; f++)
            acc[f] = fmaf(ws[f * C_DIM + c], a, acc[f]);
    }
#pragma unroll
    for (int f = 0; f < NF; f++)
        red[part * (64 * NF) + ln * NF + f] = acc[f];
    __syncthreads();

    if (which != 2) {
        uint32_t* dst32 = (which == 0) ? g_qs : g_kc;
        for (int idx = tid; idx < 64 * 5; idx += 256) {
            const int ln2 = idx / 5;
            const int p   = idx % 5;
            const int f0  = 2 * p;
            const int j0  = ln2 * NF + f0;
            float s0 = red[j0] + red[64 * NF + j0] + red[2 * 64 * NF + j0]
                     + red[3 * 64 * NF + j0] + sbias[f0];
            float s1 = red[j0 + 1] + red[64 * NF + j0 + 1] + red[2 * 64 * NF + j0 + 1]
                     + red[3 * 64 * NF + j0 + 1] + sbias[f0 + 1];
            const int nn = blockIdx.x * 64 + ln2;
            uint32_t pk = packh(s0, s1);
            if (which == 0) {
                dst32[(size_t)nn * 8 + p] = pk;
            } else {
                const int tile = nn >> 7, m = nn & 127;
                dst32[(size_t)(tile * 128 + m) * 8 + p] = pk;
            }
        }
    } else {
        // v: all 10 f-rows fp16 into [tile][f][m] (rows 10..15 stay zero)
        uint16_t* vc = reinterpret_cast<uint16_t*>(g_vc);
        for (int idx = tid; idx < 64 * NF; idx += 256) {
            const int ln2 = idx / NF;
            const int f   = idx % NF;
            const int nn  = blockIdx.x * 64 + ln2;
            const int tile = nn >> 7, m = nn & 127;
            const int j = ln2 * NF + f;
            float s = red[j] + red[64 * NF + j] + red[2 * 64 * NF + j]
                    + red[3 * 64 * NF + j] + sbias[f];
            vc[(size_t)tile * 2048 + f * 128 + m] = __half_as_ushort(__float2half_rn(s));
        }
    }
}

// ---------------- Kernel 2: mma.sync flash relu-attention (all-tensor, n=16 MMA2) ----------------
__global__ __launch_bounds__(256, 4) void attn_kernel()
{
    __shared__ __align__(16) uint32_t sK[2][128 * 12];   // padded stride 12 words
    __shared__ __align__(16) uint32_t sV[2][16 * 68];    // 16 f-rows, padded stride 68 words

    const int tid  = threadIdx.x;
    const int wid  = tid >> 5;
    const int lane = tid & 31;
    const int n0   = blockIdx.x * 128;
    const int my   = blockIdx.y;
    const int t0   = my * TILES_PER_CTA;

    const int rq = n0 + wid * 16 + (lane >> 2);
    const int l4 = lane & 3;
    uint32_t a_q[4];
    a_q[0] = g_qs[rq * 8 + l4];
    a_q[1] = g_qs[(rq + 8) * 8 + l4];
    a_q[2] = g_qs[rq * 8 + 4 + l4];
    a_q[3] = g_qs[(rq + 8) * 8 + 4 + l4];

    float O0[4] = {0.f, 0.f, 0.f, 0.f};   // f0..7 (this lane's f = 2*l4, 2*l4+1)
    float O1[4] = {0.f, 0.f, 0.f, 0.f};   // f8..15 (only l4==0 -> f8,9 real)

    // ldmatrix x4 lane-address word offsets (rows split 0-7 / 8-15, word halves)
    const uint32_t kRowOff = (uint32_t)(((lane & 7) + ((lane >> 4) << 3)) * 12 + ((lane >> 3) & 1) * 4);
    const uint32_t vRowOff = (uint32_t)(((lane & 7) + ((lane >> 4) << 3)) * 68 + ((lane >> 3) & 1) * 4);

    auto stage = [&](int buf, int tile) {
        const char* kbase = reinterpret_cast<const char*>(g_kc) + (size_t)tile * 4096;
        const char* vbase = reinterpret_cast<const char*>(g_vc) + (size_t)tile * 4096;
        {
            // K tile: 256 x 16B chunks, one per thread
            uint32_t sa = (uint32_t)__cvta_generic_to_shared(
                &sK[buf][(tid >> 1) * 12 + (tid & 1) * 4]);
            cp16(sa, kbase + tid * 16);
        }
        {
            // V tile: 256 x 16B chunks, one per thread; f = c>>4, w4 = c&15
            int f = tid >> 4, w4 = tid & 15;
            uint32_t sa = (uint32_t)__cvta_generic_to_shared(&sV[buf][f * 68 + w4 * 4]);
            cp16(sa, vbase + tid * 16);
        }
    };

    stage(0, t0);
    CP_COMMIT();

    for (int i = 0; i < TILES_PER_CTA; i++) {
        if (i + 1 < TILES_PER_CTA) {
            stage((i + 1) & 1, t0 + i + 1);
            CP_COMMIT();
            CP_WAIT(1);
        } else {
            CP_WAIT(0);
        }
        __syncthreads();

        const int buf = i & 1;
        const uint32_t kBase = (uint32_t)__cvta_generic_to_shared(&sK[buf][0]) + kRowOff * 4;
        const uint32_t vBase = (uint32_t)__cvta_generic_to_shared(&sV[buf][0]) + vRowOff * 4;

#pragma unroll
        for (int ns4 = 0; ns4 < 8; ns4++) {
            uint32_t b0, b1, b2, b3;
            ldsm4(b0, b1, b2, b3, kBase + (uint32_t)ns4 * 768);

            uint32_t p0, p1, p2, p3;
            mma_f16_h(p0, p1, a_q[0], a_q[1], a_q[2], a_q[3], b0, b1);
            mma_f16_h(p2, p3, a_q[0], a_q[1], a_q[2], a_q[3], b2, b3);

            uint32_t sh0 = relu2h(p0), sh1 = relu2h(p1);
            uint32_t sh2 = relu2h(p2), sh3 = relu2h(p3);

            // V B-fragments for n=16 (f0..7 in v0,v1; f8..15 in v2,v3)
            uint32_t v0, v1, v2, v3;
            ldsm4(v0, v1, v2, v3, vBase + (uint32_t)ns4 * 32);

            mma_f16(O0, sh0, sh1, sh2, sh3, v0, v1);
            mma_f16(O1, sh0, sh1, sh2, sh3, v2, v3);
        }
        __syncthreads();
    }

    // ---- epilogue: output-linear layout [(t*NF+f)*1024 + hw] ----
    {
        float* po = g_part + (size_t)my * PART_STRIDE;
        const int tq   = rq >> 10;
        const int hw0  = rq & 1023;            // row A; row B = hw0 + 8 (same t)
        const int base = tq * (NF * 1024) + hw0;
        const int f0   = l4 * 2;
        po[base + f0 * 1024]             = O0[0];
        po[base + (f0 + 1) * 1024]       = O0[1];
        po[base + 8 + f0 * 1024]         = O0[2];
        po[base + 8 + (f0 + 1) * 1024]   = O0[3];
        if (l4 == 0) {                        // O1 cols 8,9 are the real f8,f9
            po[base + 8 * 1024]          = O1[0];
            po[base + 9 * 1024]          = O1[1];
            po[base + 8 + 8 * 1024]      = O1[2];
            po[base + 8 + 9 * 1024]      = O1[3];
        }
    }
}

// ---------------- Kernel 3: fully-coalesced float4 reduce ----------------
__global__ __launch_bounds__(256) void reduce_kernel(float* __restrict__ out)
{
    const int idx = blockIdx.x * blockDim.x + threadIdx.x;   // < 20480 float4s
    const float4* p = reinterpret_cast<const float4*>(g_part);
    float4 s = p[idx];
#pragma unroll
    for (int c = 1; c < M_SPLIT; c++) {
        float4 v = p[(size_t)c * (PART_STRIDE / 4) + idx];
        s.x += v.x; s.y += v.y; s.z += v.z; s.w += v.w;
    }
    reinterpret_cast<float4*>(out)[idx] = s;
}

extern "C" void kernel_launch(void* const* d_in, const int* in_sizes, int n_in,
                              void* d_out, int out_size)
{
    const float* in1 = (const float*)d_in[0];
    const float* in2 = (const float*)d_in[1];
    const float* w1  = (const float*)d_in[2];
    const float* b1  = (const float*)d_in[3];
    const float* w2  = (const float*)d_in[4];
    const float* b2  = (const float*)d_in[5];
    const float* w3  = (const float*)d_in[6];
    const float* b3  = (const float*)d_in[7];

    dim3 pgrid(N_TOK / 64, 3);
    proj_kernel<<<pgrid, 256>>>(in1, in2, w1, b1, w2, b2, w3, b3);

    dim3 agrid(N_TOK / 128, M_SPLIT);
    attn_kernel<<<agrid, 256>>>();

    reduce_kernel<<<(N_TOK * NF / 4) / 256, 256>>>((float*)d_out);
}